// round 2
// baseline (speedup 1.0000x reference)
#include <cuda_runtime.h>
#include <cuda_bf16.h>
#include <math.h>

#define NP      147456      // 16*96*96
#define HW      9216        // 96*96
#define CDIM    512
#define KP      64          // protos per side
#define NSEL    256
#define NREF    10
#define TAU     0.07f
#define MARGIN  0.2f
#define MBLEND  0.3f

// ---------------- scratch (no allocations allowed) ----------------
__device__ float g_Wt[CDIM * 128];            // [c][j] transposed protos (fg||bg)
__device__ float g_score[2][NP];              // fg, bg scores
__device__ int   g_idx[2][NSEL];              // pos_idx, neg_idx (set semantics)
__device__ float g_feats[2][NSEL * CDIM];     // gathered normalized features
__device__ float g_p[2][KP * CDIM];           // refined protos (working copies)
__device__ int   g_assign[2][NSEL];
__device__ float g_simpos[NSEL], g_simneg[NSEL], g_info[NSEL];

// ---------------- kernel 0: transpose protos ----------------
__global__ void prep_wt(const float* __restrict__ fg, const float* __restrict__ bg) {
    int j = blockIdx.x;            // 0..127
    int c = threadIdx.x;           // 0..511
    float v = (j < KP) ? fg[j * CDIM + c] : bg[(j - KP) * CDIM + c];
    g_Wt[c * 128 + j] = v;
}

// ---------------- kernel 1: similarity max + scores ----------------
// block: 64 pixels x 128 protos, 128 threads, 8x8 micro-tile per thread
__global__ __launch_bounds__(128) void score_kernel(
    const float* __restrict__ F, const float* __restrict__ M) {
    __shared__ float Fsm[32 * 64];
    __shared__ float Wsm[32 * 128];
    __shared__ float red[16][64];
    __shared__ float nrmsh[128];

    int tid  = threadIdx.x;
    int px_g = tid & 7;            // pixel group (8 pixels each)
    int pr_g = tid >> 3;           // proto group (8 protos each), 0..15
    long gpix0 = (long)blockIdx.x * 64;
    int n   = (int)(gpix0 / HW);
    int hw0 = (int)(gpix0 - (long)n * HW);
    const float* Fb = F + (size_t)n * CDIM * HW + hw0;

    float acc[8][8];
#pragma unroll
    for (int i = 0; i < 8; i++)
#pragma unroll
        for (int j = 0; j < 8; j++) acc[i][j] = 0.f;

    float nrm = 0.f;
    int npix  = tid & 63;
    int nrow0 = tid >> 6;

    for (int c0 = 0; c0 < CDIM; c0 += 32) {
        // load F tile: 32 ch x 64 px
#pragma unroll
        for (int i = 0; i < 4; i++) {
            int q = tid + 128 * i;
            int r = q >> 4, c4 = (q & 15) << 2;
            *(float4*)&Fsm[r * 64 + c4] =
                *(const float4*)&Fb[(size_t)(c0 + r) * HW + c4];
        }
        // load W tile: 32 ch x 128 protos
#pragma unroll
        for (int i = 0; i < 8; i++) {
            int q = tid + 128 * i;
            int r = q >> 5, c4 = (q & 31) << 2;
            *(float4*)&Wsm[r * 128 + c4] =
                *(const float4*)&g_Wt[(size_t)(c0 + r) * 128 + c4];
        }
        __syncthreads();
        // norm partial (2 threads per pixel)
#pragma unroll
        for (int k = nrow0; k < 32; k += 2) {
            float v = Fsm[k * 64 + npix];
            nrm += v * v;
        }
        // 8x8 outer-product accumulation
#pragma unroll 8
        for (int k = 0; k < 32; k++) {
            float a[8], b[8];
            *(float4*)(a)     = *(float4*)&Fsm[k * 64 + px_g * 8];
            *(float4*)(a + 4) = *(float4*)&Fsm[k * 64 + px_g * 8 + 4];
            *(float4*)(b)     = *(float4*)&Wsm[k * 128 + pr_g * 8];
            *(float4*)(b + 4) = *(float4*)&Wsm[k * 128 + pr_g * 8 + 4];
#pragma unroll
            for (int i = 0; i < 8; i++)
#pragma unroll
                for (int j = 0; j < 8; j++)
                    acc[i][j] = fmaf(a[i], b[j], acc[i][j]);
        }
        __syncthreads();
    }

    nrmsh[tid] = nrm;
#pragma unroll
    for (int i = 0; i < 8; i++) {
        float m = acc[i][0];
#pragma unroll
        for (int j = 1; j < 8; j++) m = fmaxf(m, acc[i][j]);
        red[pr_g][px_g * 8 + i] = m;
    }
    __syncthreads();

    int p = tid & 63, side = tid >> 6;
    float m = red[side * 8][p];
#pragma unroll
    for (int g = 1; g < 8; g++) m = fmaxf(m, red[side * 8 + g][p]);
    float ss  = nrmsh[p] + nrmsh[p + 64];
    float inv = 1.0f / fmaxf(sqrtf(ss), 1e-8f);
    float sim = m * inv;
    float mv  = fminf(fmaxf(M[gpix0 + p], 0.f), 1.f);
    float d   = 1.0f - sim;
    if (side == 0) g_score[0][gpix0 + p] = d * mv;
    else           g_score[1][gpix0 + p] = d * (1.0f - mv);
}

// ---------------- kernel 2: exact top-256 (radix select) ----------------
__device__ __forceinline__ unsigned mapf(float x) {
    unsigned u = __float_as_uint(x);
    return (u & 0x80000000u) ? ~u : (u | 0x80000000u);
}

__global__ void topk_kernel() {
    int side = blockIdx.x;
    const float* s = g_score[side];
    int* out = g_idx[side];

    __shared__ unsigned hist[256];
    __shared__ unsigned sh_pfx, sh_dmask;
    __shared__ int sh_krem, sh_cgt, sh_ct;
    __shared__ int tiebuf[2048];

    if (threadIdx.x == 0) { sh_pfx = 0; sh_dmask = 0; sh_krem = NSEL; }
    __syncthreads();

    for (int shift = 24; shift >= 0; shift -= 8) {
        for (int i = threadIdx.x; i < 256; i += blockDim.x) hist[i] = 0;
        __syncthreads();
        unsigned dm = sh_dmask, pf = sh_pfx;
        for (int i = threadIdx.x; i < NP; i += blockDim.x) {
            unsigned key = mapf(s[i]);
            if ((key & dm) == pf) atomicAdd(&hist[(key >> shift) & 255], 1u);
        }
        __syncthreads();
        if (threadIdx.x == 0) {
            int kr = sh_krem;
            unsigned cum = 0;
            int d = 255;
            for (; d > 0; d--) {
                if (cum + hist[d] >= (unsigned)kr) break;
                cum += hist[d];
            }
            sh_krem  = kr - (int)cum;
            sh_pfx   = sh_pfx | ((unsigned)d << shift);
            sh_dmask = sh_dmask | (0xFFu << shift);
        }
        __syncthreads();
    }

    if (threadIdx.x == 0) { sh_cgt = 0; sh_ct = 0; }
    __syncthreads();
    unsigned thr = sh_pfx;
    for (int i = threadIdx.x; i < NP; i += blockDim.x) {
        unsigned key = mapf(s[i]);
        if (key > thr) {
            int p = atomicAdd(&sh_cgt, 1);
            if (p < NSEL) out[p] = i;
        } else if (key == thr) {
            int p = atomicAdd(&sh_ct, 1);
            if (p < 2048) tiebuf[p] = i;
        }
    }
    __syncthreads();
    if (threadIdx.x == 0) {
        int base = sh_cgt;
        int need = NSEL - base;
        int ct = sh_ct < 2048 ? sh_ct : 2048;
        for (int r = 0; r < need; r++) {          // smallest tie indices first
            int bi = 0x7FFFFFFF, best = -1;
            for (int t = 0; t < ct; t++) {
                int v = tiebuf[t];
                if (v >= 0 && v < bi) { bi = v; best = t; }
            }
            out[base + r] = bi;
            tiebuf[best] = -1;
        }
    }
}

// ---------------- kernel 3: gather + normalize selected features ----------------
__global__ void gather_kernel(const float* __restrict__ F) {
    int s = blockIdx.x, side = blockIdx.y;
    int idx = g_idx[side][s];
    int n = idx / HW, hw = idx - n * HW;
    const float* base = F + (size_t)n * CDIM * HW + hw;
    int tid = threadIdx.x;  // 128 threads
    float v[4], ss = 0.f;
#pragma unroll
    for (int i = 0; i < 4; i++) {
        int c = tid + i * 128;
        v[i] = base[(size_t)c * HW];
        ss += v[i] * v[i];
    }
#pragma unroll
    for (int o = 16; o > 0; o >>= 1) ss += __shfl_xor_sync(0xFFFFFFFFu, ss, o);
    __shared__ float wsum[4];
    if ((tid & 31) == 0) wsum[tid >> 5] = ss;
    __syncthreads();
    float tot = wsum[0] + wsum[1] + wsum[2] + wsum[3];
    float inv = 1.0f / fmaxf(sqrtf(tot), 1e-8f);
#pragma unroll
    for (int i = 0; i < 4; i++)
        g_feats[side][s * CDIM + tid + i * 128] = v[i] * inv;
}

__global__ void init_p(const float* __restrict__ fg, const float* __restrict__ bg) {
    int k = blockIdx.x, side = blockIdx.y, c = threadIdx.x;
    const float* src = side ? bg : fg;
    g_p[side][k * CDIM + c] = src[k * CDIM + c];
}

// ---------------- kernel 4: refinement assign ----------------
// 32 blocks x 8 samples; thread = (proto j, sample-pair sg); full dots per thread
__global__ void assign_kernel() {
    int side = blockIdx.y;
    int s0 = blockIdx.x * 8;
    __shared__ float fsm[8 * CDIM];
    __shared__ float dsm[8][KP];
    int tid = threadIdx.x;  // 256

    const float4* src = (const float4*)(g_feats[side] + s0 * CDIM);
#pragma unroll
    for (int i = 0; i < 4; i++)
        ((float4*)fsm)[tid + 256 * i] = src[tid + 256 * i];
    __syncthreads();

    int j = tid & 63, sg = tid >> 6;  // sg 0..3 -> samples sg*2, sg*2+1
    const float* pj = g_p[side] + j * CDIM;
    const float* fa = fsm + (sg * 2) * CDIM;
    const float* fb = fa + CDIM;
    float d0 = 0.f, d1 = 0.f;
    for (int c = 0; c < CDIM; c += 4) {
        float4 pv = *(const float4*)(pj + c);
        float4 av = *(const float4*)(fa + c);
        float4 bv = *(const float4*)(fb + c);
        d0 = fmaf(av.x, pv.x, fmaf(av.y, pv.y, fmaf(av.z, pv.z, fmaf(av.w, pv.w, d0))));
        d1 = fmaf(bv.x, pv.x, fmaf(bv.y, pv.y, fmaf(bv.z, pv.z, fmaf(bv.w, pv.w, d1))));
    }
    dsm[sg * 2][j] = d0;
    dsm[sg * 2 + 1][j] = d1;
    __syncthreads();
    if (tid < 8) {
        float best = dsm[tid][0];
        int bj = 0;
        for (int jj = 1; jj < KP; jj++) {
            float v = dsm[tid][jj];
            if (v > best) { best = v; bj = jj; }   // strict > : first-max like jnp.argmax
        }
        g_assign[side][s0 + tid] = bj;
    }
}

// ---------------- kernel 5: refinement update (deterministic) ----------------
__global__ void update_kernel(float step) {
    int k = blockIdx.x, side = blockIdx.y;
    int tid = threadIdx.x;  // 256, each thread 2 channels
    __shared__ int asg[NSEL];
    __shared__ float red[256];
    asg[tid] = g_assign[side][tid];
    __syncthreads();

    int c = tid;
    float s0 = 0.f, s1 = 0.f;
    int cnt = 0;
    for (int s = 0; s < NSEL; s++) {
        if (asg[s] == k) {
            cnt++;
            const float* f = g_feats[side] + s * CDIM;
            s0 += f[c];
            s1 += f[c + 256];
        }
    }
    float denom = fmaxf((float)cnt, 1.0f);
    float m0 = s0 / denom, m1 = s1 / denom;
    float p0 = g_p[side][k * CDIM + c];
    float p1 = g_p[side][k * CDIM + c + 256];
    float v0 = (1.0f - step) * p0 + step * m0;
    float v1 = (1.0f - step) * p1 + step * m1;
    red[tid] = v0 * v0 + v1 * v1;
    __syncthreads();
    for (int o = 128; o > 0; o >>= 1) {
        if (tid < o) red[tid] += red[tid + o];
        __syncthreads();
    }
    float inv = 1.0f / fmaxf(sqrtf(red[0]), 1e-8f);
    if (cnt > 0) {
        g_p[side][k * CDIM + c]       = v0 * inv;
        g_p[side][k * CDIM + c + 256] = v1 * inv;
    }
}

// ---------------- kernel 6: per-sample losses ----------------
__global__ void loss_kernel() {
    int s = blockIdx.x;
    int tid = threadIdx.x;  // 256
    __shared__ float posf[CDIM], negf[CDIM], dsm[192];
    posf[tid]       = g_feats[0][s * CDIM + tid];
    posf[tid + 256] = g_feats[0][s * CDIM + tid + 256];
    negf[tid]       = g_feats[1][s * CDIM + tid];
    negf[tid + 256] = g_feats[1][s * CDIM + tid + 256];
    __syncthreads();
    if (tid < 192) {
        int kind = tid / 64, j = tid % 64;
        const float* f = (kind == 2) ? negf : posf;
        const float* p = ((kind == 1) ? g_p[1] : g_p[0]) + j * CDIM;
        float d = 0.f;
        for (int c = 0; c < CDIM; c += 4) {
            float4 pv = *(const float4*)(p + c);
            d = fmaf(f[c], pv.x, fmaf(f[c+1], pv.y, fmaf(f[c+2], pv.z, fmaf(f[c+3], pv.w, d))));
        }
        dsm[tid] = d;
    }
    __syncthreads();
    if (tid == 0) {
        float mp = dsm[0];
        for (int j = 1; j < 64; j++) mp = fmaxf(mp, dsm[j]);
        float mb = dsm[64];
        for (int j = 65; j < 128; j++) mb = fmaxf(mb, dsm[j]);
        float mn = dsm[128];
        for (int j = 129; j < 192; j++) mn = fmaxf(mn, dsm[j]);
        g_simpos[s] = mp;
        g_simneg[s] = mn;
        // InfoNCE: pos_sim = dsm[0..64)/TAU, neg_sim = dsm[64..128)/TAU
        float a1 = mp / TAU;
        float sum1 = 0.f;
        for (int j = 0; j < 64; j++) sum1 += expf(dsm[j] / TAU - a1);
        float aall = fmaxf(mp, mb) / TAU;
        float sum2 = 0.f;
        for (int j = 0; j < 128; j++) sum2 += expf(dsm[j] / TAU - aall);
        float lse_num = a1 + logf(sum1);
        float lse_den = aall + logf(sum2);
        g_info[s] = lse_den - lse_num;   // = -(num - den)
    }
}

// ---------------- kernel 7: final loss reduction ----------------
__global__ void finalize_kernel(float* __restrict__ out) {
    int tid = threadIdx.x;  // 256
    __shared__ float r1[256], r2[256], r3[256];
    r1[tid] = g_simpos[tid];
    r2[tid] = g_simneg[tid];
    r3[tid] = g_info[tid];
    __syncthreads();
    for (int o = 128; o > 0; o >>= 1) {
        if (tid < o) { r1[tid] += r1[tid+o]; r2[tid] += r2[tid+o]; r3[tid] += r3[tid+o]; }
        __syncthreads();
    }
    if (tid == 0) {
        float mp = r1[0] / (float)NSEL;
        float mn = r2[0] / (float)NSEL;
        float mi = r3[0] / (float)NSEL;
        float loss = fmaxf(0.f, MARGIN + mn - mp) + 0.25f * mi;
        out[0] = loss;
    }
}

// ---------------- kernel 8: refined protos -> output ----------------
__global__ void refined_kernel(const float* __restrict__ fg, const float* __restrict__ bg,
                               float* __restrict__ out) {
    int k = blockIdx.x, side = blockIdx.y, c = threadIdx.x;  // 512 threads
    const float* src = side ? bg : fg;
    float orig = src[k * CDIM + c];
    float v = (1.0f - MBLEND) * orig + MBLEND * g_p[side][k * CDIM + c];
    __shared__ float red[CDIM];
    red[c] = v * v;
    __syncthreads();
    for (int o = 256; o > 0; o >>= 1) {
        if (c < o) red[c] += red[c + o];
        __syncthreads();
    }
    float inv = 1.0f / fmaxf(sqrtf(red[0]), 1e-8f);
    out[1 + side * (KP * CDIM) + k * CDIM + c] = v * inv;
}

// ---------------- launch ----------------
extern "C" void kernel_launch(void* const* d_in, const int* in_sizes, int n_in,
                              void* d_out, int out_size) {
    const float* fg = (const float*)d_in[0];   // [64,512]
    const float* bg = (const float*)d_in[1];   // [64,512]
    const float* F  = (const float*)d_in[2];   // [16,512,96,96]
    const float* M  = (const float*)d_in[3];   // [16,96,96]
    float* out = (float*)d_out;

    prep_wt<<<128, 512>>>(fg, bg);
    score_kernel<<<NP / 64, 128>>>(F, M);
    topk_kernel<<<2, 1024>>>();
    gather_kernel<<<dim3(NSEL, 2), 128>>>(F);
    init_p<<<dim3(KP, 2), 512>>>(fg, bg);
    for (int it = 0; it < NREF; it++) {
        float step = 0.1f / (1.0f + 0.5f * (float)it);
        assign_kernel<<<dim3(NSEL / 8, 2), 256>>>();
        update_kernel<<<dim3(KP, 2), 256>>>(step);
    }
    loss_kernel<<<NSEL, 256>>>();
    finalize_kernel<<<1, 256>>>(out);
    refined_kernel<<<dim3(KP, 2), 512>>>(fg, bg, out);
}